// round 9
// baseline (speedup 1.0000x reference)
#include <cuda_runtime.h>
#include <cuda_fp16.h>
#include <cstdint>

// ---------------- scratch (device globals; no allocation allowed) ----------
// Activations: fp16x2 "pair-planes": pair (ci, ci+8) within each 16-ch block;
// plane pp = (ci/16)*8 + (ci%8). One u32 per pixel per plane.
__device__ unsigned g_bufA[16777216];  // conv1 out (8,32pp,256,256)
__device__ unsigned g_bufP[8388608];   // pooled    (8,64pp,128,128)
__device__ unsigned g_bufC[16777216];  // conv3 out (8,128pp,128,128)
__device__ unsigned g_bufD[16777216];  // conv4 out sr pass
__device__ unsigned g_wpk[524288];     // packed fp16 A-fragment weights
__device__ double g_acc[3];            // 0: mse, 1: ssim, 2: perceptual

__global__ void zero_acc_kernel() { g_acc[0]=0.0; g_acc[1]=0.0; g_acc[2]=0.0; }

// ---------------- helpers ----------------
__device__ __forceinline__ float block_reduce_sum(float v, float* sh, int tid) {
    #pragma unroll
    for (int o = 16; o > 0; o >>= 1) v += __shfl_down_sync(0xffffffffu, v, o);
    if ((tid & 31) == 0) sh[tid >> 5] = v;
    __syncthreads();
    if (tid < 32) {
        v = (tid < 8) ? sh[tid] : 0.0f;
        #pragma unroll
        for (int o = 4; o > 0; o >>= 1) v += __shfl_down_sync(0xffffffffu, v, o);
    }
    return v;
}
__device__ __forceinline__ unsigned pack_h2(float lo, float hi) {
    __half2 h = __floats2half2_rn(lo, hi);
    return *(unsigned*)&h;
}
__device__ __forceinline__ float2 unpack_h2(unsigned u) {
    __half2 h = *(__half2*)&u;
    return __half22float2(h);
}
__device__ __forceinline__ float h16r(float x) {
    return __half2float(__float2half_rn(x));
}
__device__ __forceinline__ unsigned hm2(unsigned a, unsigned b) {
    __half2 r = __hmax2(*(__half2*)&a, *(__half2*)&b);
    return *(unsigned*)&r;
}
__device__ __forceinline__ void mma_f16(float* c, const uint4 a, const uint2 b) {
    asm volatile(
        "mma.sync.aligned.m16n8k16.row.col.f32.f16.f16.f32 "
        "{%0,%1,%2,%3}, {%4,%5,%6,%7}, {%8,%9}, {%0,%1,%2,%3};"
        : "+f"(c[0]), "+f"(c[1]), "+f"(c[2]), "+f"(c[3])
        : "r"(a.x), "r"(a.y), "r"(a.z), "r"(a.w), "r"(b.x), "r"(b.y));
}
__device__ __forceinline__ void cp_async4(unsigned dst, const void* src, bool ok) {
    int sz = ok ? 4 : 0;
    asm volatile("cp.async.ca.shared.global [%0], [%1], 4, %2;"
                 :: "r"(dst), "l"(src), "r"(sz));
}
__device__ __forceinline__ void cp_async16(unsigned dst, const void* src) {
    asm volatile("cp.async.cg.shared.global [%0], [%1], 16;" :: "r"(dst), "l"(src));
}
__device__ __forceinline__ void cp_commit() { asm volatile("cp.async.commit_group;"); }
template<int N> __device__ __forceinline__ void cp_wait() {
    asm volatile("cp.async.wait_group %0;" :: "n"(N));
}

// ---------------- MSE ----------------
__global__ void mse_kernel(const float* __restrict__ a, const float* __restrict__ b, int n) {
    __shared__ float sh[32];
    float s = 0.0f;
    for (int i = blockIdx.x * blockDim.x + threadIdx.x; i < n; i += gridDim.x * blockDim.x) {
        float d = a[i] - b[i];
        s = fmaf(d, d, s);
    }
    s = block_reduce_sum(s, sh, threadIdx.x);
    if (threadIdx.x == 0) atomicAdd(&g_acc[0], (double)s);
}

// ---------------- SSIM ----------------
__global__ void ssim_kernel(const float* __restrict__ x, const float* __restrict__ y) {
    __shared__ float sxt[22][23];
    __shared__ float syt[22][23];
    __shared__ float sh[32];
    int b = blockIdx.z;
    int gx0 = blockIdx.x * 16, gy0 = blockIdx.y * 16;
    const float* xb = x + (size_t)b * 65536;
    const float* yb = y + (size_t)b * 65536;
    int tid = threadIdx.y * 16 + threadIdx.x;
    for (int i = tid; i < 22 * 22; i += 256) {
        int rr = i / 22, cc = i - rr * 22;
        int gy = gy0 + rr, gx = gx0 + cc;
        float vx = 0.0f, vy = 0.0f;
        if (gy < 256 && gx < 256) { vx = xb[gy * 256 + gx]; vy = yb[gy * 256 + gx]; }
        sxt[rr][cc] = vx; syt[rr][cc] = vy;
    }
    __syncthreads();
    int i = gy0 + threadIdx.y, j = gx0 + threadIdx.x;
    float S = 0.0f;
    if (i < 250 && j < 250) {
        float sx = 0, sy = 0, sxx = 0, syy = 0, sxy = 0;
        #pragma unroll
        for (int dy = 0; dy < 7; dy++)
            #pragma unroll
            for (int dx = 0; dx < 7; dx++) {
                float a = sxt[threadIdx.y + dy][threadIdx.x + dx];
                float c = syt[threadIdx.y + dy][threadIdx.x + dx];
                sx += a; sy += c;
                sxx = fmaf(a, a, sxx); syy = fmaf(c, c, syy); sxy = fmaf(a, c, sxy);
            }
        const float inv = 1.0f / 49.0f, cn = 49.0f / 48.0f;
        float ux = sx * inv, uy = sy * inv;
        float vx  = cn * (sxx * inv - ux * ux);
        float vy  = cn * (syy * inv - uy * uy);
        float vxy = cn * (sxy * inv - ux * uy);
        const float C1 = 1e-4f, C2 = 9e-4f;
        S = ((2.0f * ux * uy + C1) * (2.0f * vxy + C2)) /
            ((ux * ux + uy * uy + C1) * (vx + vy + C2));
    }
    float tot = block_reduce_sum(S, sh, tid);
    if (tid == 0) atomicAdd(&g_acc[1], (double)tot);
}

// ---------------- conv1: 1 -> 64 ch, relu, fp16 pair-plane output ----------
__global__ void conv1_kernel(const float* __restrict__ in, const float* __restrict__ w,
                             const float* __restrict__ bias, unsigned* __restrict__ out) {
    __shared__ float sw[576];
    __shared__ float sb[64];
    int tid = threadIdx.x;
    for (int i = tid; i < 576; i += 256) sw[i] = w[i];
    if (tid < 64) sb[tid] = bias[tid];
    __syncthreads();
    int g = blockIdx.x * 256 + tid;
    int x4 = (g & 63) * 4;
    int y  = (g >> 6) & 255;
    int b  = g >> 14;
    const float* ib = in + (size_t)b * 65536;
    float inp[3][6];
    #pragma unroll
    for (int dy = 0; dy < 3; dy++) {
        int gy = y - 1 + dy;
        #pragma unroll
        for (int c = 0; c < 6; c++) {
            int gx = x4 - 1 + c;
            inp[dy][c] = ((unsigned)gy < 256u && (unsigned)gx < 256u) ? ib[gy * 256 + gx] : 0.0f;
        }
    }
    for (int s = 0; s < 4; s++) {
        for (int c = 0; c < 8; c++) {
            int coL = 16 * s + c, coH = coL + 8;
            float al0 = sb[coL], al1 = al0, al2 = al0, al3 = al0;
            float ah0 = sb[coH], ah1 = ah0, ah2 = ah0, ah3 = ah0;
            #pragma unroll
            for (int k = 0; k < 9; k++) {
                int ky = k / 3, kx = k - ky * 3;
                float wl = sw[coL * 9 + k], wh = sw[coH * 9 + k];
                al0 = fmaf(inp[ky][0 + kx], wl, al0);
                al1 = fmaf(inp[ky][1 + kx], wl, al1);
                al2 = fmaf(inp[ky][2 + kx], wl, al2);
                al3 = fmaf(inp[ky][3 + kx], wl, al3);
                ah0 = fmaf(inp[ky][0 + kx], wh, ah0);
                ah1 = fmaf(inp[ky][1 + kx], wh, ah1);
                ah2 = fmaf(inp[ky][2 + kx], wh, ah2);
                ah3 = fmaf(inp[ky][3 + kx], wh, ah3);
            }
            uint4 v;
            v.x = pack_h2(fmaxf(al0, 0.0f), fmaxf(ah0, 0.0f));
            v.y = pack_h2(fmaxf(al1, 0.0f), fmaxf(ah1, 0.0f));
            v.z = pack_h2(fmaxf(al2, 0.0f), fmaxf(ah2, 0.0f));
            v.w = pack_h2(fmaxf(al3, 0.0f), fmaxf(ah3, 0.0f));
            *(uint4*)(out + ((size_t)(b * 32 + s * 8 + c) * 65536) + (size_t)y * 256 + x4) = v;
        }
    }
}

// ---------------- weight pre-pack: fp16 m16n8k16 A-fragments ----------------
__global__ void pack_w_kernel(const float* __restrict__ w, unsigned* __restrict__ dst,
                              int Cin, int Cout) {
    int steps = Cin >> 4;
    int total = (Cout / 64) * steps * 4608;
    for (int idx = blockIdx.x * blockDim.x + threadIdx.x; idx < total;
         idx += gridDim.x * blockDim.x) {
        int reg = idx & 3;
        int k4  = (idx >> 2) & 3;
        int q   = (idx >> 4) & 7;
        int f   = (idx >> 7) & 1;
        int mw  = (idx >> 8) & 1;
        int tap = (idx >> 9) % 9;
        int rest = idx / 4608;
        int step = rest % steps;
        int cb   = rest / steps;
        int co = cb * 64 + mw * 32 + f * 16 + q + (reg & 1) * 8;
        int c  = k4 + (reg >> 1) * 4;
        int ci_lo = step * 16 + c;
        float lo = w[((size_t)co * Cin + ci_lo) * 9 + tap];
        float hi = w[((size_t)co * Cin + ci_lo + 8) * 9 + tap];
        dst[idx] = pack_h2(lo, hi);
    }
}

// ---------------- tensor-core 3x3 SAME conv (fp16 m16n8k16) ----------------
// Uniform 128-wide x 2-row strip tiles (N=256 px), 64 co per CTA, K=16/step.
// mode 0: store ; mode 1: diff-reduce vs ref ; mode 2: fused 2x2 maxpool out.
template<int W>
__global__ __launch_bounds__(256, 2) void conv_mma(
    const unsigned* __restrict__ in, const unsigned* __restrict__ wpack,
    const float* __restrict__ bias,
    unsigned* __restrict__ out, const unsigned* __restrict__ ref,
    int Cin, int Cout, int mode)
{
    constexpr int H = W;
    constexpr int HW = W * W;
    constexpr int SCOLS = 130;               // 128 + 2 halo
    constexpr int NPIX  = 4 * SCOLS;         // 4 rows (2 + 2 halo)
    constexpr int SIN_U = NPIX * 8;          // 4160 u32 per buffer
    constexpr int SW_U  = 9 * 512;           // 4608 u32 per buffer
    constexpr int STRIPS = W >> 7;

    extern __shared__ unsigned smem_u[];
    unsigned* s_in = smem_u;                 // 2 buffers
    unsigned* s_w  = smem_u + 2 * SIN_U;     // 2 buffers
    __shared__ float s_red[32];

    int tid = threadIdx.x;
    int warp = tid >> 5;
    int lane = tid & 31;
    int q  = lane >> 2;
    int k4 = lane & 3;
    int mw = warp & 1;
    int nw = warp >> 1;
    int mwoff = mw * 32;
    int nwoff = nw * 64;

    int strip = blockIdx.x % STRIPS;
    int ypair = blockIdx.x / STRIPS;
    int y0 = ypair * 2;
    int c0 = strip << 7;
    int cb  = blockIdx.y;
    int co0 = cb * 64;
    int b   = blockIdx.z;
    int steps = Cin >> 4;

    unsigned s_in_u = (unsigned)__cvta_generic_to_shared(s_in);
    unsigned s_w_u  = (unsigned)__cvta_generic_to_shared(s_w);

    int awb0 = ((mw * 2 + 0) * 8 + q) * 16 + k4 * 4;
    int awb1 = awb0 + 128;

    int bb[8];
    #pragma unroll
    for (int nf = 0; nf < 8; nf++) {
        int base = nwoff + nf * 8;
        int ry   = base >> 7;
        int col  = base & 127;
        bb[nf] = ((ry * SCOLS + col) + q) * 8 + 2 * k4;
    }

    float acc[2][8][4];
    #pragma unroll
    for (int f = 0; f < 2; f++)
        #pragma unroll
        for (int nf = 0; nf < 8; nf++)
            #pragma unroll
            for (int e = 0; e < 4; e++) acc[f][nf][e] = 0.0f;

    const unsigned* inb = in + (size_t)b * (Cin >> 1) * HW;
    const unsigned* wblk = wpack + (size_t)cb * steps * 4608;

    auto stage = [&](int step, int buf) {
        const unsigned* pbase = inb + (size_t)step * 8 * HW;
        unsigned ibase = s_in_u + buf * SIN_U * 4;
        #pragma unroll 4
        for (int i = tid; i < NPIX * 8; i += 256) {
            int p = i >> 3;
            int c = i & 7;
            int r = p / SCOLS, cc = p - r * SCOLS;
            int gy = y0 - 1 + r;
            int gx = c0 + cc - 1;
            bool ok = ((unsigned)gy < (unsigned)H) && ((unsigned)gx < (unsigned)W);
            const unsigned* src = pbase + (size_t)c * HW + (ok ? (gy * W + gx) : 0);
            int slot = ((c & 3) << 1) + (c >> 2);
            cp_async4(ibase + (unsigned)(p * 8 + slot) * 4, src, ok);
        }
        unsigned wbase = s_w_u + buf * SW_U * 4;
        const unsigned* wsrc = wblk + (size_t)step * 4608;
        #pragma unroll
        for (int i = tid; i < 1152; i += 256)
            cp_async16(wbase + (unsigned)i * 16, wsrc + i * 4);
    };

    stage(0, 0);
    cp_commit();

    for (int s = 0; s < steps; s++) {
        int cur = s & 1;
        if (s + 1 < steps) {
            stage(s + 1, cur ^ 1);
            cp_commit();
            cp_wait<1>();
        } else {
            cp_wait<0>();
        }
        __syncthreads();

        const unsigned* bin = s_in + cur * SIN_U;
        const unsigned* bw  = s_w  + cur * SW_U;

        #pragma unroll
        for (int tap = 0; tap < 9; tap++) {
            const int ky = tap / 3, kx = tap - ky * 3;
            const int toff = (ky * SCOLS + kx) * 8;
            uint4 af0 = *(const uint4*)(bw + tap * 512 + awb0);
            uint4 af1 = *(const uint4*)(bw + tap * 512 + awb1);
            #pragma unroll
            for (int nf = 0; nf < 8; nf++) {
                uint2 bv = *(const uint2*)(bin + bb[nf] + toff);
                mma_f16(acc[0][nf], af0, bv);
                mma_f16(acc[1][nf], af1, bv);
            }
        }
        __syncthreads();
    }

    // ---- epilogue ----
    if (mode == 0) {
        #pragma unroll
        for (int f = 0; f < 2; f++) {
            int coL = co0 + mwoff + f * 16 + q;
            float bv0 = __ldg(&bias[coL]);
            float bv8 = __ldg(&bias[coL + 8]);
            int pp = ((co0 + mwoff + f * 16) >> 4) * 8 + q;
            unsigned* pl = out + (size_t)(b * (Cout >> 1) + pp) * HW;
            #pragma unroll
            for (int nf = 0; nf < 8; nf++) {
                int n = nwoff + nf * 8 + 2 * k4;
                int idx = (y0 + (n >> 7)) * W + c0 + (n & 127);
                uint2 v;
                v.x = pack_h2(fmaxf(acc[f][nf][0] + bv0, 0.0f),
                              fmaxf(acc[f][nf][2] + bv8, 0.0f));
                v.y = pack_h2(fmaxf(acc[f][nf][1] + bv0, 0.0f),
                              fmaxf(acc[f][nf][3] + bv8, 0.0f));
                *(uint2*)(pl + idx) = v;
            }
        }
    } else if (mode == 1) {
        float lsum = 0.0f;
        #pragma unroll
        for (int f = 0; f < 2; f++) {
            int coL = co0 + mwoff + f * 16 + q;
            float bv0 = __ldg(&bias[coL]);
            float bv8 = __ldg(&bias[coL + 8]);
            int pp = ((co0 + mwoff + f * 16) >> 4) * 8 + q;
            const unsigned* pl = ref + (size_t)(b * (Cout >> 1) + pp) * HW;
            #pragma unroll
            for (int nf = 0; nf < 8; nf++) {
                int n = nwoff + nf * 8 + 2 * k4;
                int idx = (y0 + (n >> 7)) * W + c0 + (n & 127);
                uint2 rv = *(const uint2*)(pl + idx);
                float2 r0 = unpack_h2(rv.x);
                float2 r1 = unpack_h2(rv.y);
                float d0 = h16r(fmaxf(acc[f][nf][0] + bv0, 0.0f)) - r0.x;
                float d1 = h16r(fmaxf(acc[f][nf][2] + bv8, 0.0f)) - r0.y;
                float d2 = h16r(fmaxf(acc[f][nf][1] + bv0, 0.0f)) - r1.x;
                float d3 = h16r(fmaxf(acc[f][nf][3] + bv8, 0.0f)) - r1.y;
                lsum = fmaf(d0, d0, lsum);
                lsum = fmaf(d1, d1, lsum);
                lsum = fmaf(d2, d2, lsum);
                lsum = fmaf(d3, d3, lsum);
            }
        }
        float tot = block_reduce_sum(lsum, s_red, tid);
        if (tid == 0) atomicAdd(&g_acc[2], (double)tot);
    } else {
        // mode 2: fused 2x2 maxpool (conv2). Reuse staging smem as pool buffer.
        __syncthreads();
        unsigned* spool = s_in;   // [2 rows][128 x][32 co-pairs] u32 (8192 <= 8320)
        #pragma unroll
        for (int f = 0; f < 2; f++) {
            int coL = co0 + mwoff + f * 16 + q;
            float bv0 = __ldg(&bias[coL]);
            float bv8 = __ldg(&bias[coL + 8]);
            int lp = ((mwoff + f * 16) >> 4) * 8 + q;     // 0..31 local pair
            #pragma unroll
            for (int nf = 0; nf < 8; nf++) {
                int n = nwoff + nf * 8 + 2 * k4;
                int row = n >> 7, x = n & 127;
                spool[(row * 128 + x) * 32 + lp] =
                    pack_h2(fmaxf(acc[f][nf][0] + bv0, 0.0f),
                            fmaxf(acc[f][nf][2] + bv8, 0.0f));
                spool[(row * 128 + x + 1) * 32 + lp] =
                    pack_h2(fmaxf(acc[f][nf][1] + bv0, 0.0f),
                            fmaxf(acc[f][nf][3] + bv8, 0.0f));
            }
        }
        __syncthreads();
        int ypix = ypair * 128 + (c0 >> 1);   // pooled pixel base
        for (int i = tid; i < 2048; i += 256) {
            int lp = i >> 6;
            int X  = i & 63;
            unsigned m = hm2(hm2(spool[(2 * X) * 32 + lp],
                                 spool[(2 * X + 1) * 32 + lp]),
                             hm2(spool[(128 + 2 * X) * 32 + lp],
                                 spool[(129 + 2 * X) * 32 + lp]));
            out[((size_t)b * 64 + cb * 32 + lp) * 16384 + ypix + X] = m;
        }
    }
}

// ---------------- finalize ----------------
__global__ void finalize_kernel(float* out, int out_size) {
    double mse    = g_acc[0] / 524288.0;
    double ssim_l = 1.0 - g_acc[1] / 500000.0;
    double perc   = g_acc[2] / 33554432.0;
    double total  = mse + 0.5 * ssim_l + 0.1 * perc;
    float vals[4] = {(float)total, (float)mse, (float)ssim_l, (float)perc};
    for (int i = 0; i < 4 && i < out_size; i++) out[i] = vals[i];
}

// ---------------- launcher ----------------
extern "C" void kernel_launch(void* const* d_in, const int* in_sizes, int n_in,
                              void* d_out, int out_size) {
    (void)in_sizes; (void)n_in;
    const float* sr = (const float*)d_in[0];
    const float* hr = (const float*)d_in[1];
    const float* w1 = (const float*)d_in[2];
    const float* b1 = (const float*)d_in[3];
    const float* w2 = (const float*)d_in[4];
    const float* b2 = (const float*)d_in[5];
    const float* w3 = (const float*)d_in[6];
    const float* b3 = (const float*)d_in[7];
    const float* w4 = (const float*)d_in[8];
    const float* b4 = (const float*)d_in[9];
    float* out = (float*)d_out;

    unsigned *A, *P, *C, *D, *WP;
    cudaGetSymbolAddress((void**)&A, g_bufA);
    cudaGetSymbolAddress((void**)&P, g_bufP);
    cudaGetSymbolAddress((void**)&C, g_bufC);
    cudaGetSymbolAddress((void**)&D, g_bufD);
    cudaGetSymbolAddress((void**)&WP, g_wpk);
    unsigned* WP2 = WP;             // 2*4*4608  = 36864 u32
    unsigned* WP3 = WP + 36864;     // 4*8*4608  = 147456 u32
    unsigned* WP4 = WP + 184320;    // 4*16*4608 = 294912 u32

    const int smem = (2 * 4160 + 2 * 4608) * 4;   // 70144 B
    cudaFuncSetAttribute(conv_mma<256>, cudaFuncAttributeMaxDynamicSharedMemorySize, smem);
    cudaFuncSetAttribute(conv_mma<128>, cudaFuncAttributeMaxDynamicSharedMemorySize, smem);

    // Launch order arranged so launch index 5 (ncu -s 5 -c 1) = conv_mma (conv3).
    zero_acc_kernel<<<1, 1>>>();                       // 0
    pack_w_kernel<<<144, 256>>>(w2, WP2, 64, 128);     // 1
    conv1_kernel<<<512, 256>>>(sr, w1, b1, A);         // 2
    conv_mma<256><<<dim3(256, 2, 8), 256, smem>>>(A, WP2, b2, P, nullptr,
                                                  64, 128, 2);        // 3 conv2+pool
    pack_w_kernel<<<576, 256>>>(w3, WP3, 128, 256);    // 4
    conv_mma<128><<<dim3(64, 4, 8), 256, smem>>>(P, WP3, b3, C, nullptr,
                                                 128, 256, 0);        // 5 conv3
    pack_w_kernel<<<1152, 256>>>(w4, WP4, 256, 256);   // 6
    conv_mma<128><<<dim3(64, 4, 8), 256, smem>>>(C, WP4, b4, D, nullptr,
                                                 256, 256, 0);        // 7 conv4-sr
    mse_kernel<<<512, 256>>>(sr, hr, 524288);          // 8
    ssim_kernel<<<dim3(16, 16, 8), dim3(16, 16)>>>(sr, hr);  // 9

    // hr pass
    conv1_kernel<<<512, 256>>>(hr, w1, b1, A);
    conv_mma<256><<<dim3(256, 2, 8), 256, smem>>>(A, WP2, b2, P, nullptr, 64, 128, 2);
    conv_mma<128><<<dim3(64, 4, 8), 256, smem>>>(P, WP3, b3, C, nullptr, 128, 256, 0);
    conv_mma<128><<<dim3(64, 4, 8), 256, smem>>>(C, WP4, b4, nullptr, D, 256, 256, 1);

    finalize_kernel<<<1, 1>>>(out, out_size);
}

// round 10
// speedup vs baseline: 1.2875x; 1.2875x over previous
#include <cuda_runtime.h>
#include <cuda_fp16.h>
#include <cstdint>

// ---------------- scratch (device globals; no allocation allowed) ----------
// Activations: [b][plane=16ch][HW px][8 u32 record], record = slot-permuted
// fp16x2 pairs: slot(c) = (c&3)*2+(c>>2) holds channels (c, c+8), c=0..7.
__device__ unsigned g_bufA[16777216];  // conv1 out (8,4pl,65536,8)
__device__ unsigned g_bufP[8388608];   // pooled    (8,8pl,16384,8)
__device__ unsigned g_bufC[16777216];  // conv3 out (8,16pl,16384,8)
__device__ unsigned g_bufD[16777216];  // conv4 out sr pass
__device__ unsigned g_wpk[524288];     // packed fp16 A-fragment weights
__device__ double g_acc[3];            // 0: mse, 1: ssim, 2: perceptual

__global__ void zero_acc_kernel() { g_acc[0]=0.0; g_acc[1]=0.0; g_acc[2]=0.0; }

// ---------------- helpers ----------------
__device__ __forceinline__ float block_reduce_sum(float v, float* sh, int tid) {
    #pragma unroll
    for (int o = 16; o > 0; o >>= 1) v += __shfl_down_sync(0xffffffffu, v, o);
    if ((tid & 31) == 0) sh[tid >> 5] = v;
    __syncthreads();
    if (tid < 32) {
        v = (tid < 8) ? sh[tid] : 0.0f;
        #pragma unroll
        for (int o = 4; o > 0; o >>= 1) v += __shfl_down_sync(0xffffffffu, v, o);
    }
    return v;
}
__device__ __forceinline__ unsigned pack_h2(float lo, float hi) {
    __half2 h = __floats2half2_rn(lo, hi);
    return *(unsigned*)&h;
}
__device__ __forceinline__ float2 unpack_h2(unsigned u) {
    __half2 h = *(__half2*)&u;
    return __half22float2(h);
}
__device__ __forceinline__ float h16r(float x) {
    return __half2float(__float2half_rn(x));
}
__device__ __forceinline__ unsigned hm2(unsigned a, unsigned b) {
    __half2 r = __hmax2(*(__half2*)&a, *(__half2*)&b);
    return *(unsigned*)&r;
}
__device__ __forceinline__ void mma_f16(float* c, const uint4 a, const uint2 b) {
    asm volatile(
        "mma.sync.aligned.m16n8k16.row.col.f32.f16.f16.f32 "
        "{%0,%1,%2,%3}, {%4,%5,%6,%7}, {%8,%9}, {%0,%1,%2,%3};"
        : "+f"(c[0]), "+f"(c[1]), "+f"(c[2]), "+f"(c[3])
        : "r"(a.x), "r"(a.y), "r"(a.z), "r"(a.w), "r"(b.x), "r"(b.y));
}
__device__ __forceinline__ void cp_async16(unsigned dst, const void* src) {
    asm volatile("cp.async.cg.shared.global [%0], [%1], 16;" :: "r"(dst), "l"(src));
}
__device__ __forceinline__ void cp_async16z(unsigned dst, const void* src, bool ok) {
    int sz = ok ? 16 : 0;
    asm volatile("cp.async.cg.shared.global [%0], [%1], 16, %2;"
                 :: "r"(dst), "l"(src), "r"(sz));
}
__device__ __forceinline__ void cp_commit() { asm volatile("cp.async.commit_group;"); }
template<int N> __device__ __forceinline__ void cp_wait() {
    asm volatile("cp.async.wait_group %0;" :: "n"(N));
}
__device__ __forceinline__ int slot_of(int c) { return ((c & 3) << 1) + (c >> 2); }

// ---------------- MSE ----------------
__global__ void mse_kernel(const float* __restrict__ a, const float* __restrict__ b, int n) {
    __shared__ float sh[32];
    float s = 0.0f;
    for (int i = blockIdx.x * blockDim.x + threadIdx.x; i < n; i += gridDim.x * blockDim.x) {
        float d = a[i] - b[i];
        s = fmaf(d, d, s);
    }
    s = block_reduce_sum(s, sh, threadIdx.x);
    if (threadIdx.x == 0) atomicAdd(&g_acc[0], (double)s);
}

// ---------------- SSIM ----------------
__global__ void ssim_kernel(const float* __restrict__ x, const float* __restrict__ y) {
    __shared__ float sxt[22][23];
    __shared__ float syt[22][23];
    __shared__ float sh[32];
    int b = blockIdx.z;
    int gx0 = blockIdx.x * 16, gy0 = blockIdx.y * 16;
    const float* xb = x + (size_t)b * 65536;
    const float* yb = y + (size_t)b * 65536;
    int tid = threadIdx.y * 16 + threadIdx.x;
    for (int i = tid; i < 22 * 22; i += 256) {
        int rr = i / 22, cc = i - rr * 22;
        int gy = gy0 + rr, gx = gx0 + cc;
        float vx = 0.0f, vy = 0.0f;
        if (gy < 256 && gx < 256) { vx = xb[gy * 256 + gx]; vy = yb[gy * 256 + gx]; }
        sxt[rr][cc] = vx; syt[rr][cc] = vy;
    }
    __syncthreads();
    int i = gy0 + threadIdx.y, j = gx0 + threadIdx.x;
    float S = 0.0f;
    if (i < 250 && j < 250) {
        float sx = 0, sy = 0, sxx = 0, syy = 0, sxy = 0;
        #pragma unroll
        for (int dy = 0; dy < 7; dy++)
            #pragma unroll
            for (int dx = 0; dx < 7; dx++) {
                float a = sxt[threadIdx.y + dy][threadIdx.x + dx];
                float c = syt[threadIdx.y + dy][threadIdx.x + dx];
                sx += a; sy += c;
                sxx = fmaf(a, a, sxx); syy = fmaf(c, c, syy); sxy = fmaf(a, c, sxy);
            }
        const float inv = 1.0f / 49.0f, cn = 49.0f / 48.0f;
        float ux = sx * inv, uy = sy * inv;
        float vx  = cn * (sxx * inv - ux * ux);
        float vy  = cn * (syy * inv - uy * uy);
        float vxy = cn * (sxy * inv - ux * uy);
        const float C1 = 1e-4f, C2 = 9e-4f;
        S = ((2.0f * ux * uy + C1) * (2.0f * vxy + C2)) /
            ((ux * ux + uy * uy + C1) * (vx + vy + C2));
    }
    float tot = block_reduce_sum(S, sh, tid);
    if (tid == 0) atomicAdd(&g_acc[1], (double)tot);
}

// ---------------- conv1: 1 -> 64 ch, relu, 32B pixel records ----------
__global__ void conv1_kernel(const float* __restrict__ in, const float* __restrict__ w,
                             const float* __restrict__ bias, unsigned* __restrict__ out) {
    __shared__ float sw[576];
    __shared__ float sb[64];
    int tid = threadIdx.x;
    for (int i = tid; i < 576; i += 256) sw[i] = w[i];
    if (tid < 64) sb[tid] = bias[tid];
    __syncthreads();
    int g = blockIdx.x * 256 + tid;
    int x4 = (g & 63) * 4;
    int y  = (g >> 6) & 255;
    int b  = g >> 14;
    const float* ib = in + (size_t)b * 65536;
    float inp[3][6];
    #pragma unroll
    for (int dy = 0; dy < 3; dy++) {
        int gy = y - 1 + dy;
        #pragma unroll
        for (int c = 0; c < 6; c++) {
            int gx = x4 - 1 + c;
            inp[dy][c] = ((unsigned)gy < 256u && (unsigned)gx < 256u) ? ib[gy * 256 + gx] : 0.0f;
        }
    }
    for (int blk = 0; blk < 4; blk++) {
        unsigned rec[4][8];
        for (int c = 0; c < 8; c++) {
            int coL = 16 * blk + c, coH = coL + 8;
            float aL[4], aH[4];
            #pragma unroll
            for (int p = 0; p < 4; p++) { aL[p] = sb[coL]; aH[p] = sb[coH]; }
            #pragma unroll
            for (int k = 0; k < 9; k++) {
                int ky = k / 3, kx = k - ky * 3;
                float wl = sw[coL * 9 + k], wh = sw[coH * 9 + k];
                #pragma unroll
                for (int p = 0; p < 4; p++) {
                    aL[p] = fmaf(inp[ky][p + kx], wl, aL[p]);
                    aH[p] = fmaf(inp[ky][p + kx], wh, aH[p]);
                }
            }
            int s = slot_of(c);
            #pragma unroll
            for (int p = 0; p < 4; p++)
                rec[p][s] = pack_h2(fmaxf(aL[p], 0.0f), fmaxf(aH[p], 0.0f));
        }
        #pragma unroll
        for (int p = 0; p < 4; p++) {
            size_t base = (((size_t)(b * 4 + blk)) * 65536 + (size_t)y * 256 + x4 + p) * 8;
            *(uint4*)(out + base)     = make_uint4(rec[p][0], rec[p][1], rec[p][2], rec[p][3]);
            *(uint4*)(out + base + 4) = make_uint4(rec[p][4], rec[p][5], rec[p][6], rec[p][7]);
        }
    }
}

// ---------------- weight pre-pack: fp16 m16n8k16 A-fragments ----------------
__global__ void pack_w_kernel(const float* __restrict__ w, unsigned* __restrict__ dst,
                              int Cin, int Cout) {
    int steps = Cin >> 4;
    int total = (Cout / 64) * steps * 4608;
    for (int idx = blockIdx.x * blockDim.x + threadIdx.x; idx < total;
         idx += gridDim.x * blockDim.x) {
        int reg = idx & 3;
        int k4  = (idx >> 2) & 3;
        int q   = (idx >> 4) & 7;
        int f   = (idx >> 7) & 1;
        int mw  = (idx >> 8) & 1;
        int tap = (idx >> 9) % 9;
        int rest = idx / 4608;
        int step = rest % steps;
        int cb   = rest / steps;
        int co = cb * 64 + mw * 32 + f * 16 + q + (reg & 1) * 8;
        int c  = k4 + (reg >> 1) * 4;
        int ci_lo = step * 16 + c;
        float lo = w[((size_t)co * Cin + ci_lo) * 9 + tap];
        float hi = w[((size_t)co * Cin + ci_lo + 8) * 9 + tap];
        dst[idx] = pack_h2(lo, hi);
    }
}

// ---------------- tensor-core 3x3 SAME conv (fp16 m16n8k16) ----------------
// Uniform 128x2 strips (N=256 px), 64 co per CTA, K=16/step.
// mode 0: store ; 1: diff-reduce vs ref ; 2: fused 2x2 maxpool out.
template<int W>
__global__ __launch_bounds__(256, 2) void conv_mma(
    const unsigned* __restrict__ in, const unsigned* __restrict__ wpack,
    const float* __restrict__ bias,
    unsigned* __restrict__ out, const unsigned* __restrict__ ref,
    int Cin, int Cout, int mode)
{
    constexpr int H = W;
    constexpr int HW = W * W;
    constexpr int SCOLS = 130;
    constexpr int NPIX  = 4 * SCOLS;         // 520
    constexpr int SIN_U = NPIX * 8;          // 4160
    constexpr int SW_U  = 9 * 512;           // 4608
    constexpr int STRIPS = W >> 7;

    extern __shared__ unsigned smem_u[];
    unsigned* s_in = smem_u;
    unsigned* s_w  = smem_u + 2 * SIN_U;
    __shared__ float s_red[32];

    int tid = threadIdx.x;
    int warp = tid >> 5;
    int lane = tid & 31;
    int q  = lane >> 2;
    int k4 = lane & 3;
    int mw = warp & 1;
    int nw = warp >> 1;
    int mwoff = mw * 32;
    int nwoff = nw * 64;

    int strip = blockIdx.x % STRIPS;
    int ypair = blockIdx.x / STRIPS;
    int y0 = ypair * 2;
    int c0 = strip << 7;
    int cb  = blockIdx.y;
    int co0 = cb * 64;
    int b   = blockIdx.z;
    int steps = Cin >> 4;

    unsigned s_in_u = (unsigned)__cvta_generic_to_shared(s_in);
    unsigned s_w_u  = (unsigned)__cvta_generic_to_shared(s_w);

    int awb0 = ((mw * 2 + 0) * 8 + q) * 16 + k4 * 4;
    int awb1 = awb0 + 128;

    int bb[8];
    #pragma unroll
    for (int nf = 0; nf < 8; nf++) {
        int base = nwoff + nf * 8;
        int ry   = base >> 7;
        int col  = base & 127;
        bb[nf] = ((ry * SCOLS + col) + q) * 8 + 2 * k4;
    }

    float acc[2][8][4];
    #pragma unroll
    for (int f = 0; f < 2; f++)
        #pragma unroll
        for (int nf = 0; nf < 8; nf++)
            #pragma unroll
            for (int e = 0; e < 4; e++) acc[f][nf][e] = 0.0f;

    const unsigned* inb = in + (size_t)b * (Cin >> 4) * HW * 8;
    const unsigned* wblk = wpack + (size_t)cb * steps * 4608;

    auto stage = [&](int step, int buf) {
        const unsigned* pbase = inb + (size_t)step * HW * 8;
        unsigned ibase = s_in_u + buf * SIN_U * 4;
        #pragma unroll 4
        for (int i = tid; i < NPIX * 2; i += 256) {
            int p = i >> 1;
            int half = i & 1;
            int r = p / SCOLS, cc = p - r * SCOLS;
            int gy = y0 - 1 + r;
            int gx = c0 + cc - 1;
            bool ok = ((unsigned)gy < (unsigned)H) && ((unsigned)gx < (unsigned)W);
            const unsigned* src = pbase + (size_t)(ok ? (gy * W + gx) : 0) * 8 + half * 4;
            cp_async16z(ibase + (unsigned)(p * 8 + half * 4) * 4, src, ok);
        }
        unsigned wbase = s_w_u + buf * SW_U * 4;
        const unsigned* wsrc = wblk + (size_t)step * 4608;
        #pragma unroll
        for (int i = tid; i < 1152; i += 256)
            cp_async16(wbase + (unsigned)i * 16, wsrc + i * 4);
    };

    stage(0, 0);
    cp_commit();

    for (int s = 0; s < steps; s++) {
        int cur = s & 1;
        if (s + 1 < steps) {
            stage(s + 1, cur ^ 1);
            cp_commit();
            cp_wait<1>();
        } else {
            cp_wait<0>();
        }
        __syncthreads();

        const unsigned* bin = s_in + cur * SIN_U;
        const unsigned* bw  = s_w  + cur * SW_U;

        #pragma unroll
        for (int tap = 0; tap < 9; tap++) {
            const int ky = tap / 3, kx = tap - ky * 3;
            const int toff = (ky * SCOLS + kx) * 8;
            uint4 af0 = *(const uint4*)(bw + tap * 512 + awb0);
            uint4 af1 = *(const uint4*)(bw + tap * 512 + awb1);
            #pragma unroll
            for (int nf = 0; nf < 8; nf++) {
                uint2 bv = *(const uint2*)(bin + bb[nf] + toff);
                mma_f16(acc[0][nf], af0, bv);
                mma_f16(acc[1][nf], af1, bv);
            }
        }
        __syncthreads();
    }

    // ---- epilogue ----
    int sl = slot_of(q);
    if (mode == 0) {
        #pragma unroll
        for (int f = 0; f < 2; f++) {
            int coL = co0 + mwoff + f * 16 + q;
            float bv0 = __ldg(&bias[coL]);
            float bv8 = __ldg(&bias[coL + 8]);
            int plane = (co0 + mwoff + f * 16) >> 4;
            unsigned* pl = out + ((size_t)b * (Cout >> 4) + plane) * HW * 8;
            #pragma unroll
            for (int nf = 0; nf < 8; nf++) {
                int n = nwoff + nf * 8 + 2 * k4;
                int idx = (y0 + (n >> 7)) * W + c0 + (n & 127);
                pl[(size_t)idx * 8 + sl] =
                    pack_h2(fmaxf(acc[f][nf][0] + bv0, 0.0f),
                            fmaxf(acc[f][nf][2] + bv8, 0.0f));
                pl[(size_t)(idx + 1) * 8 + sl] =
                    pack_h2(fmaxf(acc[f][nf][1] + bv0, 0.0f),
                            fmaxf(acc[f][nf][3] + bv8, 0.0f));
            }
        }
    } else if (mode == 1) {
        float lsum = 0.0f;
        #pragma unroll
        for (int f = 0; f < 2; f++) {
            int coL = co0 + mwoff + f * 16 + q;
            float bv0 = __ldg(&bias[coL]);
            float bv8 = __ldg(&bias[coL + 8]);
            int plane = (co0 + mwoff + f * 16) >> 4;
            const unsigned* pl = ref + ((size_t)b * (Cout >> 4) + plane) * HW * 8;
            #pragma unroll
            for (int nf = 0; nf < 8; nf++) {
                int n = nwoff + nf * 8 + 2 * k4;
                int idx = (y0 + (n >> 7)) * W + c0 + (n & 127);
                float2 r0 = unpack_h2(pl[(size_t)idx * 8 + sl]);
                float2 r1 = unpack_h2(pl[(size_t)(idx + 1) * 8 + sl]);
                float d0 = h16r(fmaxf(acc[f][nf][0] + bv0, 0.0f)) - r0.x;
                float d1 = h16r(fmaxf(acc[f][nf][2] + bv8, 0.0f)) - r0.y;
                float d2 = h16r(fmaxf(acc[f][nf][1] + bv0, 0.0f)) - r1.x;
                float d3 = h16r(fmaxf(acc[f][nf][3] + bv8, 0.0f)) - r1.y;
                lsum = fmaf(d0, d0, lsum);
                lsum = fmaf(d1, d1, lsum);
                lsum = fmaf(d2, d2, lsum);
                lsum = fmaf(d3, d3, lsum);
            }
        }
        float tot = block_reduce_sum(lsum, s_red, tid);
        if (tid == 0) atomicAdd(&g_acc[2], (double)tot);
    } else {
        // mode 2: fused 2x2 maxpool (conv2, W=256). spool[(row*128+x)*32 + lp]
        __syncthreads();
        unsigned* spool = s_in;
        #pragma unroll
        for (int f = 0; f < 2; f++) {
            int coL = co0 + mwoff + f * 16 + q;
            float bv0 = __ldg(&bias[coL]);
            float bv8 = __ldg(&bias[coL + 8]);
            int lp = ((mwoff + f * 16) >> 4) * 8 + q;
            #pragma unroll
            for (int nf = 0; nf < 8; nf++) {
                int n = nwoff + nf * 8 + 2 * k4;
                int row = n >> 7, x = n & 127;
                spool[(row * 128 + x) * 32 + lp] =
                    pack_h2(fmaxf(acc[f][nf][0] + bv0, 0.0f),
                            fmaxf(acc[f][nf][2] + bv8, 0.0f));
                spool[(row * 128 + x + 1) * 32 + lp] =
                    pack_h2(fmaxf(acc[f][nf][1] + bv0, 0.0f),
                            fmaxf(acc[f][nf][3] + bv8, 0.0f));
            }
        }
        __syncthreads();
        int ypix = ypair * 128 + (c0 >> 1);
        for (int i = tid; i < 2048; i += 256) {
            int lp = i >> 6;
            int X  = i & 63;
            unsigned m = hm2(hm2(spool[(2 * X) * 32 + lp],
                                 spool[(2 * X + 1) * 32 + lp]),
                             hm2(spool[(128 + 2 * X) * 32 + lp],
                                 spool[(129 + 2 * X) * 32 + lp]));
            int pl_loc = lp >> 3, c = lp & 7;
            out[(((size_t)b * 8 + cb * 4 + pl_loc) * 16384
                 + (size_t)(ypix + X)) * 8 + slot_of(c)] = m;
        }
    }
}

// ---------------- finalize ----------------
__global__ void finalize_kernel(float* out, int out_size) {
    double mse    = g_acc[0] / 524288.0;
    double ssim_l = 1.0 - g_acc[1] / 500000.0;
    double perc   = g_acc[2] / 33554432.0;
    double total  = mse + 0.5 * ssim_l + 0.1 * perc;
    float vals[4] = {(float)total, (float)mse, (float)ssim_l, (float)perc};
    for (int i = 0; i < 4 && i < out_size; i++) out[i] = vals[i];
}

// ---------------- launcher ----------------
extern "C" void kernel_launch(void* const* d_in, const int* in_sizes, int n_in,
                              void* d_out, int out_size) {
    (void)in_sizes; (void)n_in;
    const float* sr = (const float*)d_in[0];
    const float* hr = (const float*)d_in[1];
    const float* w1 = (const float*)d_in[2];
    const float* b1 = (const float*)d_in[3];
    const float* w2 = (const float*)d_in[4];
    const float* b2 = (const float*)d_in[5];
    const float* w3 = (const float*)d_in[6];
    const float* b3 = (const float*)d_in[7];
    const float* w4 = (const float*)d_in[8];
    const float* b4 = (const float*)d_in[9];
    float* out = (float*)d_out;

    unsigned *A, *P, *C, *D, *WP;
    cudaGetSymbolAddress((void**)&A, g_bufA);
    cudaGetSymbolAddress((void**)&P, g_bufP);
    cudaGetSymbolAddress((void**)&C, g_bufC);
    cudaGetSymbolAddress((void**)&D, g_bufD);
    cudaGetSymbolAddress((void**)&WP, g_wpk);
    unsigned* WP2 = WP;             // 36864 u32
    unsigned* WP3 = WP + 36864;     // 147456 u32
    unsigned* WP4 = WP + 184320;    // 294912 u32

    const int smem = (2 * 4160 + 2 * 4608) * 4;   // 70144 B
    cudaFuncSetAttribute(conv_mma<256>, cudaFuncAttributeMaxDynamicSharedMemorySize, smem);
    cudaFuncSetAttribute(conv_mma<128>, cudaFuncAttributeMaxDynamicSharedMemorySize, smem);

    zero_acc_kernel<<<1, 1>>>();
    pack_w_kernel<<<144, 256>>>(w2, WP2, 64, 128);
    conv1_kernel<<<512, 256>>>(sr, w1, b1, A);
    conv_mma<256><<<dim3(256, 2, 8), 256, smem>>>(A, WP2, b2, P, nullptr, 64, 128, 2);
    pack_w_kernel<<<576, 256>>>(w3, WP3, 128, 256);
    conv_mma<128><<<dim3(64, 4, 8), 256, smem>>>(P, WP3, b3, C, nullptr, 128, 256, 0);
    pack_w_kernel<<<1152, 256>>>(w4, WP4, 256, 256);
    conv_mma<128><<<dim3(64, 4, 8), 256, smem>>>(C, WP4, b4, D, nullptr, 256, 256, 0);
    mse_kernel<<<512, 256>>>(sr, hr, 524288);
    ssim_kernel<<<dim3(16, 16, 8), dim3(16, 16)>>>(sr, hr);

    // hr pass
    conv1_kernel<<<512, 256>>>(hr, w1, b1, A);
    conv_mma<256><<<dim3(256, 2, 8), 256, smem>>>(A, WP2, b2, P, nullptr, 64, 128, 2);
    conv_mma<128><<<dim3(64, 4, 8), 256, smem>>>(P, WP3, b3, C, nullptr, 128, 256, 0);
    conv_mma<128><<<dim3(64, 4, 8), 256, smem>>>(C, WP4, b4, nullptr, D, 256, 256, 1);

    finalize_kernel<<<1, 1>>>(out, out_size);
}